// round 7
// baseline (speedup 1.0000x reference)
#include <cuda_runtime.h>

// Problem constants
#define K_COLORS 512
#define CHUNK    32
#define NCHUNK   (K_COLORS / CHUNK)   // 16
#define GRP      (CHUNK / 4)          // 8 four-color groups per chunk
#define HW       65536                // 256*256
#define B        8
#define PPT      4                    // pixels (batch images) per thread
#define NTHREADS 128
#define NBLOCKS  1024                 // 131072 threads = HW * (B/PPT)
#define NPIX     (HW * B)             // 524288
#define NOUT     (NPIX * 3)           // 1572864

// Precomputed palette, filled by prep_kernel each launch.
// SoA pair layout: element g4 covers colors 4*g4..4*g4+3 as two f32x2 pairs.
__device__ ulonglong2 gA0[K_COLORS / 4];   // -2*t0
__device__ ulonglong2 gA1[K_COLORS / 4];   // -2*t1
__device__ ulonglong2 gA2[K_COLORS / 4];   // -2*t2
__device__ ulonglong2 gNN[K_COLORS / 4];   // ||t||^2
__device__ float4     gC4[K_COLORS];       // AoS (-2t0,-2t1,-2t2,n) for rescan

__device__ float        g_partials[NBLOCKS];
__device__ unsigned int g_count = 0;

// ---- packed f32x2 helpers ----
__device__ __forceinline__ unsigned long long fma2(unsigned long long a,
                                                   unsigned long long b,
                                                   unsigned long long c) {
    unsigned long long d;
    asm("fma.rn.f32x2 %0, %1, %2, %3;" : "=l"(d) : "l"(a), "l"(b), "l"(c));
    return d;
}
__device__ __forceinline__ unsigned long long bc2(float x) {
    unsigned int u = __float_as_uint(x);
    return ((unsigned long long)u << 32) | u;
}
__device__ __forceinline__ float lo_f(unsigned long long v) {
    return __uint_as_float((unsigned int)v);
}
__device__ __forceinline__ float hi_f(unsigned long long v) {
    return __uint_as_float((unsigned int)(v >> 32));
}

__global__ void __launch_bounds__(K_COLORS) prep_kernel(
    const float* __restrict__ table)
{
    const int k = threadIdx.x;
    float t0 = table[3 * k + 0];
    float t1 = table[3 * k + 1];
    float t2 = table[3 * k + 2];
    float n  = __fadd_rn(__fadd_rn(__fmul_rn(t0, t0), __fmul_rn(t1, t1)),
                         __fmul_rn(t2, t2));
    float a0 = -2.0f * t0, a1 = -2.0f * t1, a2 = -2.0f * t2;
    ((float*)gA0)[k] = a0;
    ((float*)gA1)[k] = a1;
    ((float*)gA2)[k] = a2;
    ((float*)gNN)[k] = n;
    gC4[k] = make_float4(a0, a1, a2, n);
}

// Fused VQ + straight-through output + loss.
//
// Palette coefficients read via __ldg from global (uniform LDG.128: the
// coalescer dedups 32 identical lane addresses to ONE sector request, unlike
// LDS broadcast which pays full 512B crossbar traffic — rounds 1-6 were
// smem-wavefront bound). float4/ulonglong2 loads land in aligned register
// quads, so the two f32x2 halves need no repacking.
//
// Inner loop per 4 colors per pixel: 6 FFMA2 + 4 FMNMX (value-only tracking).
// Index recovery is hierarchical and exact (bit-validated in rounds 4/6):
//   - per 32-color chunk, strict '<' commit in ascending chunk order;
//   - winning chunk rescanned with the bit-identical scalar FMA chain,
//     first '==' match wins (jnp.argmin first-index semantics).
__global__ void __launch_bounds__(NTHREADS) vq_kernel(
    const float* __restrict__ z,
    float* __restrict__ out,
    int out_size)
{
    __shared__ float sred[NTHREADS];
    __shared__ int   s_last;

    const int tid  = threadIdx.x;
    const int g    = blockIdx.x * NTHREADS + tid;   // 0..131071
    const int hw   = g & (HW - 1);
    const int bat0 = (g >> 16) * PPT;               // first batch image

    // Pixel components broadcast into both packed halves (loop-invariant).
    unsigned long long Xb[PPT], Yb[PPT], Zb[PPT];
#pragma unroll
    for (int p = 0; p < PPT; ++p) {
        const int base = (bat0 + p) * 3 * HW + hw;
        Xb[p] = bc2(z[base]);
        Yb[p] = bc2(z[base + HW]);
        Zb[p] = bc2(z[base + 2 * HW]);
    }

    float gbest[PPT];
    int   gch[PPT];
#pragma unroll
    for (int p = 0; p < PPT; ++p) { gbest[p] = 3.402823466e38f; gch[p] = 0; }

    for (int c = 0; c < NCHUNK; ++c) {
        float cmlo[PPT], cmhi[PPT];
#pragma unroll
        for (int p = 0; p < PPT; ++p) {
            cmlo[p] = 3.402823466e38f;
            cmhi[p] = 3.402823466e38f;
        }

#pragma unroll 8
        for (int q = 0; q < GRP; ++q) {
            const int g4 = c * GRP + q;            // colors 4*g4 .. 4*g4+3
            const ulonglong2 a0 = __ldg(&gA0[g4]);
            const ulonglong2 a1 = __ldg(&gA1[g4]);
            const ulonglong2 a2 = __ldg(&gA2[g4]);
            const ulonglong2 nn = __ldg(&gNN[g4]);
#pragma unroll
            for (int p = 0; p < PPT; ++p) {
                // d = x*(-2t0) + (y*(-2t1) + (z*(-2t2) + n)) — same chain
                // order/rounding as the reference scalar fmaf chain.
                unsigned long long d01 =
                    fma2(Xb[p], a0.x, fma2(Yb[p], a1.x, fma2(Zb[p], a2.x, nn.x)));
                unsigned long long d23 =
                    fma2(Xb[p], a0.y, fma2(Yb[p], a1.y, fma2(Zb[p], a2.y, nn.y)));
                cmlo[p] = fminf(cmlo[p], fminf(lo_f(d01), lo_f(d23)));
                cmhi[p] = fminf(cmhi[p], fminf(hi_f(d01), hi_f(d23)));
            }
        }
        // Chunk commit: strict '<' keeps the EARLIEST chunk on exact ties.
#pragma unroll
        for (int p = 0; p < PPT; ++p) {
            float m  = fminf(cmlo[p], cmhi[p]);
            bool lt  = m < gbest[p];
            gbest[p] = fminf(gbest[p], m);
            gch[p]   = lt ? c : gch[p];
        }
    }

    // Exact index recovery (first '==' match inside the winning chunk),
    // fused with the STE epilogue + loss accumulation.
    float lsum = 0.0f;
#pragma unroll
    for (int p = 0; p < PPT; ++p) {
        const int   kb = gch[p] << 5;
        const float px = lo_f(Xb[p]);
        const float py = lo_f(Yb[p]);
        const float pz = lo_f(Zb[p]);
        int found = 1023;
#pragma unroll 8
        for (int i = 0; i < CHUNK; ++i) {
            const float4 cc = __ldg(&gC4[kb + i]);
            float d = fmaf(px, cc.x, fmaf(py, cc.y, fmaf(pz, cc.z, cc.w)));
            int kc = (d == gbest[p]) ? (kb + i) : 1023;
            found  = min(found, kc);
        }
        const float4 cc = __ldg(&gC4[found]);
        float q0 = -0.5f * cc.x;                 // exact recovery of t from -2t
        float q1 = -0.5f * cc.y;
        float q2 = -0.5f * cc.z;
        float d0 = __fsub_rn(q0, px);
        float d1 = __fsub_rn(q1, py);
        float d2 = __fsub_rn(q2, pz);
        const int base = (bat0 + p) * 3 * HW + hw;
        out[base]          = __fadd_rn(px, d0);  // zl + (z_q - zl)
        out[base + HW]     = __fadd_rn(py, d1);
        out[base + 2 * HW] = __fadd_rn(pz, d2);
        lsum = fmaf(d0, d0, lsum);
        lsum = fmaf(d1, d1, lsum);
        lsum = fmaf(d2, d2, lsum);
    }

    // Deterministic block reduction.
    sred[tid] = lsum;
    __syncthreads();
#pragma unroll
    for (int s = NTHREADS / 2; s > 0; s >>= 1) {
        if (tid < s) sred[tid] += sred[tid + s];
        __syncthreads();
    }

    // Last-block-done final reduction (single fused kernel).
    if (tid == 0) {
        g_partials[blockIdx.x] = sred[0];
        __threadfence();
        unsigned int prev = atomicAdd(&g_count, 1u);
        s_last = (prev == NBLOCKS - 1) ? 1 : 0;
    }
    __syncthreads();

    if (s_last) {
        __threadfence();
        volatile float* vp = g_partials;
        float acc = 0.0f;
        for (int i = tid; i < NBLOCKS; i += NTHREADS) acc += vp[i];
        sred[tid] = acc;
        __syncthreads();
#pragma unroll
        for (int s = NTHREADS / 2; s > 0; s >>= 1) {
            if (tid < s) sred[tid] += sred[tid + s];
            __syncthreads();
        }
        if (tid == 0) {
            float m    = sred[0] / (float)NOUT;
            float loss = __fadd_rn(10.0f * m, m);
            for (int i = NOUT; i < out_size; ++i) out[i] = loss;
            g_count = 0;   // reset for the next graph replay
        }
    }
}

extern "C" void kernel_launch(void* const* d_in, const int* in_sizes, int n_in,
                              void* d_out, int out_size)
{
    const float* z     = (const float*)d_in[0];
    const float* table = (const float*)d_in[1];
    float* out         = (float*)d_out;

    prep_kernel<<<1, K_COLORS>>>(table);
    vq_kernel<<<NBLOCKS, NTHREADS>>>(z, out, out_size);
}

// round 8
// speedup vs baseline: 1.1270x; 1.1270x over previous
#include <cuda_runtime.h>

// Problem constants
#define K_COLORS 512
#define CHUNK    32
#define NCHUNK   (K_COLORS / CHUNK)   // 16
#define GRP      (CHUNK / 4)          // 8 four-color groups per chunk
#define NGRP     (K_COLORS / 4)       // 128
#define HW       65536                // 256*256
#define B        8
#define PPT      4                    // pixels (batch images) per thread
#define NTHREADS 128
#define NBLOCKS  1024                 // 131072 threads = HW * (B/PPT)
#define NPIX     (HW * B)             // 524288
#define NOUT     (NPIX * 3)           // 1572864

// One group = 4 consecutive colors, coefficients pre-paired for f32x2 math:
// a0 = {(-2t0_k,-2t0_k+1),(-2t0_k+2,-2t0_k+3)}, likewise a1/a2/nn.
struct Grp { ulonglong2 a0, a1, a2, nn; };

__constant__ Grp   cG[NGRP];          // main-loop palette (const port, no L1tex)
__device__   Grp   gG[NGRP];          // staging, written by prep_kernel
__device__   float4 gC4[K_COLORS];    // AoS (-2t0,-2t1,-2t2,n) for the rescan

__device__ float        g_partials[NBLOCKS];
__device__ unsigned int g_count = 0;

// ---- packed f32x2 helpers ----
__device__ __forceinline__ unsigned long long fma2(unsigned long long a,
                                                   unsigned long long b,
                                                   unsigned long long c) {
    unsigned long long d;
    asm("fma.rn.f32x2 %0, %1, %2, %3;" : "=l"(d) : "l"(a), "l"(b), "l"(c));
    return d;
}
__device__ __forceinline__ unsigned long long bc2(float x) {
    unsigned int u = __float_as_uint(x);
    return ((unsigned long long)u << 32) | u;
}
__device__ __forceinline__ float lo_f(unsigned long long v) {
    return __uint_as_float((unsigned int)v);
}
__device__ __forceinline__ float hi_f(unsigned long long v) {
    return __uint_as_float((unsigned int)(v >> 32));
}

__global__ void __launch_bounds__(K_COLORS) prep_kernel(
    const float* __restrict__ table)
{
    const int k = threadIdx.x;
    float t0 = table[3 * k + 0];
    float t1 = table[3 * k + 1];
    float t2 = table[3 * k + 2];
    float n  = __fadd_rn(__fadd_rn(__fmul_rn(t0, t0), __fmul_rn(t1, t1)),
                         __fmul_rn(t2, t2));
    float a0 = -2.0f * t0, a1 = -2.0f * t1, a2 = -2.0f * t2;
    // Scatter scalars into the paired group layout.
    const int g4 = k >> 2, lane = k & 3;
    float* base = (float*)&gG[g4];
    base[0 * 4 + lane] = a0;    // a0 pair block
    base[1 * 4 + lane] = a1;
    base[2 * 4 + lane] = a2;
    base[3 * 4 + lane] = n;
    gC4[k] = make_float4(a0, a1, a2, n);
}

// Fused VQ + straight-through output + loss.
//
// KEY CHANGE vs rounds 1-7 (all L1tex-wavefront bound at 59-76% L1): the
// main-loop palette reads now come from __constant__ memory with a
// warp-UNIFORM index (the loop counter). Constant loads use the dedicated
// const-cache port (LDC/LDCU), NOT the L1tex pipeline — palette traffic
// leaves the bottleneck pipe entirely. The divergent rescan stays on __ldg
// (divergent LDC would serialize per unique address).
//
// Inner loop per 4 colors per pixel: 6 FFMA2 + 4 FMNMX (value-only).
// Index recovery is hierarchical and exact (bit-validated rounds 4/6/7):
//   - per 32-color chunk, strict '<' commit in ascending chunk order;
//   - winning chunk rescanned with the bit-identical scalar FMA chain,
//     first '==' match wins (jnp.argmin first-index semantics).
__global__ void __launch_bounds__(NTHREADS) vq_kernel(
    const float* __restrict__ z,
    float* __restrict__ out,
    int out_size)
{
    __shared__ float sred[NTHREADS];
    __shared__ int   s_last;

    const int tid  = threadIdx.x;
    const int g    = blockIdx.x * NTHREADS + tid;   // 0..131071
    const int hw   = g & (HW - 1);
    const int bat0 = (g >> 16) * PPT;               // first batch image

    // Pixel components broadcast into both packed halves (loop-invariant).
    unsigned long long Xb[PPT], Yb[PPT], Zb[PPT];
#pragma unroll
    for (int p = 0; p < PPT; ++p) {
        const int base = (bat0 + p) * 3 * HW + hw;
        Xb[p] = bc2(z[base]);
        Yb[p] = bc2(z[base + HW]);
        Zb[p] = bc2(z[base + 2 * HW]);
    }

    float gbest[PPT];
    int   gch[PPT];
#pragma unroll
    for (int p = 0; p < PPT; ++p) { gbest[p] = 3.402823466e38f; gch[p] = 0; }

    for (int c = 0; c < NCHUNK; ++c) {
        float cmlo[PPT], cmhi[PPT];
#pragma unroll
        for (int p = 0; p < PPT; ++p) {
            cmlo[p] = 3.402823466e38f;
            cmhi[p] = 3.402823466e38f;
        }

#pragma unroll
        for (int q = 0; q < GRP; ++q) {
            const Grp gr = cG[c * GRP + q];        // uniform index -> const port
#pragma unroll
            for (int p = 0; p < PPT; ++p) {
                // d = x*(-2t0) + (y*(-2t1) + (z*(-2t2) + n)) — same chain
                // order/rounding as the reference scalar fmaf chain.
                unsigned long long d01 =
                    fma2(Xb[p], gr.a0.x,
                         fma2(Yb[p], gr.a1.x, fma2(Zb[p], gr.a2.x, gr.nn.x)));
                unsigned long long d23 =
                    fma2(Xb[p], gr.a0.y,
                         fma2(Yb[p], gr.a1.y, fma2(Zb[p], gr.a2.y, gr.nn.y)));
                cmlo[p] = fminf(cmlo[p], fminf(lo_f(d01), lo_f(d23)));
                cmhi[p] = fminf(cmhi[p], fminf(hi_f(d01), hi_f(d23)));
            }
        }
        // Chunk commit: strict '<' keeps the EARLIEST chunk on exact ties.
#pragma unroll
        for (int p = 0; p < PPT; ++p) {
            float m  = fminf(cmlo[p], cmhi[p]);
            bool lt  = m < gbest[p];
            gbest[p] = fminf(gbest[p], m);
            gch[p]   = lt ? c : gch[p];
        }
    }

    // Exact index recovery (first '==' match inside the winning chunk),
    // fused with the STE epilogue + loss accumulation.
    float lsum = 0.0f;
#pragma unroll
    for (int p = 0; p < PPT; ++p) {
        const int   kb = gch[p] << 5;
        const float px = lo_f(Xb[p]);
        const float py = lo_f(Yb[p]);
        const float pz = lo_f(Zb[p]);
        int found = 1023;
#pragma unroll 8
        for (int i = 0; i < CHUNK; ++i) {
            const float4 cc = __ldg(&gC4[kb + i]);
            float d = fmaf(px, cc.x, fmaf(py, cc.y, fmaf(pz, cc.z, cc.w)));
            int kc = (d == gbest[p]) ? (kb + i) : 1023;
            found  = min(found, kc);
        }
        const float4 cc = __ldg(&gC4[found]);
        float q0 = -0.5f * cc.x;                 // exact recovery of t from -2t
        float q1 = -0.5f * cc.y;
        float q2 = -0.5f * cc.z;
        float d0 = __fsub_rn(q0, px);
        float d1 = __fsub_rn(q1, py);
        float d2 = __fsub_rn(q2, pz);
        const int base = (bat0 + p) * 3 * HW + hw;
        out[base]          = __fadd_rn(px, d0);  // zl + (z_q - zl)
        out[base + HW]     = __fadd_rn(py, d1);
        out[base + 2 * HW] = __fadd_rn(pz, d2);
        lsum = fmaf(d0, d0, lsum);
        lsum = fmaf(d1, d1, lsum);
        lsum = fmaf(d2, d2, lsum);
    }

    // Deterministic block reduction.
    sred[tid] = lsum;
    __syncthreads();
#pragma unroll
    for (int s = NTHREADS / 2; s > 0; s >>= 1) {
        if (tid < s) sred[tid] += sred[tid + s];
        __syncthreads();
    }

    // Last-block-done final reduction (single fused kernel).
    if (tid == 0) {
        g_partials[blockIdx.x] = sred[0];
        __threadfence();
        unsigned int prev = atomicAdd(&g_count, 1u);
        s_last = (prev == NBLOCKS - 1) ? 1 : 0;
    }
    __syncthreads();

    if (s_last) {
        __threadfence();
        volatile float* vp = g_partials;
        float acc = 0.0f;
        for (int i = tid; i < NBLOCKS; i += NTHREADS) acc += vp[i];
        sred[tid] = acc;
        __syncthreads();
#pragma unroll
        for (int s = NTHREADS / 2; s > 0; s >>= 1) {
            if (tid < s) sred[tid] += sred[tid + s];
            __syncthreads();
        }
        if (tid == 0) {
            float m    = sred[0] / (float)NOUT;
            float loss = __fadd_rn(10.0f * m, m);
            for (int i = NOUT; i < out_size; ++i) out[i] = loss;
            g_count = 0;   // reset for the next graph replay
        }
    }
}

extern "C" void kernel_launch(void* const* d_in, const int* in_sizes, int n_in,
                              void* d_out, int out_size)
{
    const float* z     = (const float*)d_in[0];
    const float* table = (const float*)d_in[1];
    float* out         = (float*)d_out;

    prep_kernel<<<1, K_COLORS>>>(table);

    // Stage -> constant bank, device-to-device async (graph-capturable).
    void* gG_addr = nullptr;
    cudaGetSymbolAddress(&gG_addr, gG);
    cudaMemcpyToSymbolAsync(cG, gG_addr, sizeof(gG), 0,
                            cudaMemcpyDeviceToDevice, 0);

    vq_kernel<<<NBLOCKS, NTHREADS>>>(z, out, out_size);
}

// round 9
// speedup vs baseline: 1.6919x; 1.5012x over previous
#include <cuda_runtime.h>

// Problem constants
#define K_COLORS 512
#define NGRP     (K_COLORS / 4)       // 128 groups of 4 colors
#define HW       65536                // 256*256
#define B        8
#define PPT      4                    // pixels (batch images) per thread
#define NTHREADS 128
#define NBLOCKS  1024                 // 131072 threads = HW * (B/PPT)
#define NPIX     (HW * B)             // 524288
#define NOUT     (NPIX * 3)           // 1572864

// One group = 4 consecutive colors, coefficients pre-paired for f32x2 math:
// a0 = {(-2t0_k,-2t0_k+1),(-2t0_k+2,-2t0_k+3)}, likewise a1/a2/nn.
struct Grp { ulonglong2 a0, a1, a2, nn; };

__constant__ Grp    cG[NGRP];         // main-loop palette (const port, no L1tex)
__device__   Grp    gG[NGRP];         // staging, written by prep_kernel
__device__   float4 gC4[K_COLORS];    // AoS (-2t0,-2t1,-2t2,n) for the rescan

__device__ float        g_partials[NBLOCKS];
__device__ unsigned int g_count = 0;

// ---- packed f32x2 helpers ----
__device__ __forceinline__ unsigned long long fma2(unsigned long long a,
                                                   unsigned long long b,
                                                   unsigned long long c) {
    unsigned long long d;
    asm("fma.rn.f32x2 %0, %1, %2, %3;" : "=l"(d) : "l"(a), "l"(b), "l"(c));
    return d;
}
__device__ __forceinline__ unsigned long long bc2(float x) {
    unsigned int u = __float_as_uint(x);
    return ((unsigned long long)u << 32) | u;
}
__device__ __forceinline__ float lo_f(unsigned long long v) {
    return __uint_as_float((unsigned int)v);
}
__device__ __forceinline__ float hi_f(unsigned long long v) {
    return __uint_as_float((unsigned int)(v >> 32));
}

__global__ void __launch_bounds__(K_COLORS) prep_kernel(
    const float* __restrict__ table)
{
    const int k = threadIdx.x;
    float t0 = table[3 * k + 0];
    float t1 = table[3 * k + 1];
    float t2 = table[3 * k + 2];
    float n  = __fadd_rn(__fadd_rn(__fmul_rn(t0, t0), __fmul_rn(t1, t1)),
                         __fmul_rn(t2, t2));
    float a0 = -2.0f * t0, a1 = -2.0f * t1, a2 = -2.0f * t2;
    const int g4 = k >> 2, lane = k & 3;
    float* base = (float*)&gG[g4];
    base[0 * 4 + lane] = a0;
    base[1 * 4 + lane] = a1;
    base[2 * 4 + lane] = a2;
    base[3 * 4 + lane] = n;
    gC4[k] = make_float4(a0, a1, a2, n);
}

// Fused VQ + straight-through output + loss.
//
// Main loop: palette from __constant__ with warp-uniform index (const port,
// off the L1tex pipeline). Per 4-color group per pixel: 6 FFMA2 for the four
// distances, 3 FMNMX to reduce them, then strict-'<' commit of (min, group)
// in ascending group order.
//
// KEY CHANGE vs round 8: recovery granularity is a 4-color GROUP, not a
// 32-color chunk. The divergent final rescan shrinks 8x (16 vs 128 LDG.128
// per thread) — profiling showed that divergent rescan gather was ~half of
// all L1tex wavefront traffic in every prior round.
//
// Exactness: strict '<' keeps the earliest group on exact ties; within the
// group the scalar FMA chain is bit-identical to the packed halves (same op
// order), so the first '==' match is the argmin with jnp.argmin first-index
// semantics. Same scheme bit-validated in rounds 4/6/7/8.
__global__ void __launch_bounds__(NTHREADS) vq_kernel(
    const float* __restrict__ z,
    float* __restrict__ out,
    int out_size)
{
    __shared__ float sred[NTHREADS];
    __shared__ int   s_last;

    const int tid  = threadIdx.x;
    const int g    = blockIdx.x * NTHREADS + tid;   // 0..131071
    const int hw   = g & (HW - 1);
    const int bat0 = (g >> 16) * PPT;               // first batch image

    // Pixel components broadcast into both packed halves (loop-invariant).
    unsigned long long Xb[PPT], Yb[PPT], Zb[PPT];
#pragma unroll
    for (int p = 0; p < PPT; ++p) {
        const int base = (bat0 + p) * 3 * HW + hw;
        Xb[p] = bc2(z[base]);
        Yb[p] = bc2(z[base + HW]);
        Zb[p] = bc2(z[base + 2 * HW]);
    }

    float gbest[PPT];
    int   ggrp[PPT];
#pragma unroll
    for (int p = 0; p < PPT; ++p) { gbest[p] = 3.402823466e38f; ggrp[p] = 0; }

#pragma unroll 8
    for (int g4 = 0; g4 < NGRP; ++g4) {
        const Grp gr = cG[g4];                     // uniform -> const port
#pragma unroll
        for (int p = 0; p < PPT; ++p) {
            // d = x*(-2t0) + (y*(-2t1) + (z*(-2t2) + n)) — same chain
            // order/rounding as the reference scalar fmaf chain.
            unsigned long long d01 =
                fma2(Xb[p], gr.a0.x,
                     fma2(Yb[p], gr.a1.x, fma2(Zb[p], gr.a2.x, gr.nn.x)));
            unsigned long long d23 =
                fma2(Xb[p], gr.a0.y,
                     fma2(Yb[p], gr.a1.y, fma2(Zb[p], gr.a2.y, gr.nn.y)));
            float m = fminf(fminf(lo_f(d01), hi_f(d01)),
                            fminf(lo_f(d23), hi_f(d23)));
            bool lt  = m < gbest[p];               // earliest group on ties
            gbest[p] = fminf(gbest[p], m);
            ggrp[p]  = lt ? g4 : ggrp[p];
        }
    }

    // Exact index recovery (first '==' match inside the winning 4-color
    // group), fused with the STE epilogue + loss accumulation.
    float lsum = 0.0f;
#pragma unroll
    for (int p = 0; p < PPT; ++p) {
        const int   kb = ggrp[p] << 2;
        const float px = lo_f(Xb[p]);
        const float py = lo_f(Yb[p]);
        const float pz = lo_f(Zb[p]);
        int found = 1023;
#pragma unroll
        for (int i = 0; i < 4; ++i) {
            const float4 cc = __ldg(&gC4[kb + i]);
            float d = fmaf(px, cc.x, fmaf(py, cc.y, fmaf(pz, cc.z, cc.w)));
            int kc = (d == gbest[p]) ? (kb + i) : 1023;
            found  = min(found, kc);
        }
        const float4 cc = __ldg(&gC4[found]);
        float q0 = -0.5f * cc.x;                 // exact recovery of t from -2t
        float q1 = -0.5f * cc.y;
        float q2 = -0.5f * cc.z;
        float d0 = __fsub_rn(q0, px);
        float d1 = __fsub_rn(q1, py);
        float d2 = __fsub_rn(q2, pz);
        const int base = (bat0 + p) * 3 * HW + hw;
        out[base]          = __fadd_rn(px, d0);  // zl + (z_q - zl)
        out[base + HW]     = __fadd_rn(py, d1);
        out[base + 2 * HW] = __fadd_rn(pz, d2);
        lsum = fmaf(d0, d0, lsum);
        lsum = fmaf(d1, d1, lsum);
        lsum = fmaf(d2, d2, lsum);
    }

    // Deterministic block reduction.
    sred[tid] = lsum;
    __syncthreads();
#pragma unroll
    for (int s = NTHREADS / 2; s > 0; s >>= 1) {
        if (tid < s) sred[tid] += sred[tid + s];
        __syncthreads();
    }

    // Last-block-done final reduction (single fused kernel).
    if (tid == 0) {
        g_partials[blockIdx.x] = sred[0];
        __threadfence();
        unsigned int prev = atomicAdd(&g_count, 1u);
        s_last = (prev == NBLOCKS - 1) ? 1 : 0;
    }
    __syncthreads();

    if (s_last) {
        __threadfence();
        volatile float* vp = g_partials;
        float acc = 0.0f;
        for (int i = tid; i < NBLOCKS; i += NTHREADS) acc += vp[i];
        sred[tid] = acc;
        __syncthreads();
#pragma unroll
        for (int s = NTHREADS / 2; s > 0; s >>= 1) {
            if (tid < s) sred[tid] += sred[tid + s];
            __syncthreads();
        }
        if (tid == 0) {
            float m    = sred[0] / (float)NOUT;
            float loss = __fadd_rn(10.0f * m, m);
            for (int i = NOUT; i < out_size; ++i) out[i] = loss;
            g_count = 0;   // reset for the next graph replay
        }
    }
}

extern "C" void kernel_launch(void* const* d_in, const int* in_sizes, int n_in,
                              void* d_out, int out_size)
{
    const float* z     = (const float*)d_in[0];
    const float* table = (const float*)d_in[1];
    float* out         = (float*)d_out;

    prep_kernel<<<1, K_COLORS>>>(table);

    // Stage -> constant bank, device-to-device async (graph-capturable).
    void* gG_addr = nullptr;
    cudaGetSymbolAddress(&gG_addr, gG);
    cudaMemcpyToSymbolAsync(cG, gG_addr, sizeof(gG), 0,
                            cudaMemcpyDeviceToDevice, 0);

    vq_kernel<<<NBLOCKS, NTHREADS>>>(z, out, out_size);
}